// round 12
// baseline (speedup 1.0000x reference)
#include <cuda_runtime.h>
#include <cuda_bf16.h>

// Problem constants (fixed by setup_inputs)
#define HEIGHT 256
#define WIDTH  256
#define NBATCH 128
#define NK     4
#define NPAR   28
#define PIX    (HEIGHT * WIDTH)
#define PPT    32                      // pixels per thread (16 packed pairs)
#define THREADS 256
#define PPB    (THREADS * PPT)         // 8192 pixels per block

typedef unsigned long long u64;

// ---- packed f32x2 helpers (sm_103a FFMA2 path, PTX-only) ----
__device__ __forceinline__ u64 pk2(float lo, float hi) {
    u64 r; asm("mov.b64 %0, {%1, %2};" : "=l"(r) : "f"(lo), "f"(hi)); return r;
}
__device__ __forceinline__ void upk2(u64 v, float& lo, float& hi) {
    asm("mov.b64 {%0, %1}, %2;" : "=f"(lo), "=f"(hi) : "l"(v));
}
__device__ __forceinline__ u64 fma2(u64 a, u64 b, u64 c) {
    u64 d; asm("fma.rn.f32x2 %0, %1, %2, %3;" : "=l"(d) : "l"(a), "l"(b), "l"(c)); return d;
}
__device__ __forceinline__ u64 mul2(u64 a, u64 b) {
    u64 d; asm("mul.rn.f32x2 %0, %1, %2;" : "=l"(d) : "l"(a), "l"(b)); return d;
}
__device__ __forceinline__ u64 add2(u64 a, u64 b) {
    u64 d; asm("add.rn.f32x2 %0, %1, %2;" : "=l"(d) : "l"(a), "l"(b)); return d;
}
__device__ __forceinline__ float fast_ex2(float x) {
    float r; asm("ex2.approx.f32 %0, %1;" : "=f"(r) : "f"(x)); return r;
}

__global__ __launch_bounds__(THREADS, 4)
void moe_gauss_kernel(const float* __restrict__ params, float* __restrict__ out) {
    const int b   = blockIdx.y;
    const int p0  = blockIdx.x * PPB + threadIdx.x * PPT;
    const int row = p0 >> 8;           // all 32 pixels share the same row (32 | 256)
    const int j0  = p0 & 255;

    const float* __restrict__ p = params + b * NPAR;

    const float dl = 1.0f / 255.0f;    // grid step
    const float x  = (float)row * dl;
    const float h  = 0.7213475204444817f;   // 0.5 * log2(e)

    const float y_lo = (float)j0 * dl;
    const float y_hi = (float)(j0 + 1) * dl;

    // Geometric recurrence over the packed pixel-pair sequence (stride 2*dl):
    //   f(y) = al*y^2 + be*y + ga   (the ex2 argument, -h factor folded in)
    //   e_{n+1} = e_n * r_n,  r_{n+1} = r_n * q
    //   r(y) = ex2(f(y+2d) - f(y)) = ex2(4*al*d*y + 4*al*d^2 + 2*be*d)
    //   q    = ex2(8*al*d^2)                       (lane-independent constant)
    // => zero EX2 in the pixel loop; 5 EX2 per Gaussian in the preamble.
    u64 E2[NK], R2[NK], Q2[NK], W2[NK];
#pragma unroll
    for (int k = 0; k < NK; k++) {
        const float mux = __ldg(p + k);
        const float muy = __ldg(p + NK + k);
        const float wk  = __ldg(p + 2 * NK + k);
        const float A   = __ldg(p + 3 * NK + 4 * k + 0);   // s00
        const float C   = __ldg(p + 3 * NK + 4 * k + 2);   // s10
        const float D   = __ldg(p + 3 * NK + 4 * k + 3);   // s11

        const float t   = x - mux;
        const float b0  = fmaf(t, A, -muy * C);
        const float b1  = -muy * D;
        const float al  = -h * fmaf(C, C, D * D);
        const float be  = -2.0f * h * fmaf(C, b0, D * b1);
        const float ga  = -h * fmaf(b0, b0, b1 * b1);

        const float f_lo = fmaf(fmaf(al, y_lo, be), y_lo, ga);
        const float f_hi = fmaf(fmaf(al, y_hi, be), y_hi, ga);
        E2[k] = pk2(fast_ex2(f_lo), fast_ex2(f_hi));

        const float ald  = al * dl;
        const float rc   = fmaf(4.0f * ald, dl, 2.0f * be * dl);  // 4*al*d^2 + 2*be*d
        const float r_lo = fmaf(4.0f * ald, y_lo, rc);
        const float r_hi = fmaf(4.0f * ald, y_hi, rc);
        R2[k] = pk2(fast_ex2(r_lo), fast_ex2(r_hi));

        const float q = fast_ex2(8.0f * ald * dl);                // ex2(8*al*d^2)
        Q2[k] = pk2(q, q);
        W2[k] = pk2(wk, wk);
    }

    float* dst = out + (size_t)b * PIX + p0;

#pragma unroll
    for (int v = 0; v < PPT / 4; v++) {
        float4 r4;
        float* rp = &r4.x;
#pragma unroll
        for (int q = 0; q < 2; q++) {
            u64 g2 = 0ull;   // packed {0.0f, 0.0f}
            u64 a2 = 0ull;
#pragma unroll
            for (int k = 0; k < NK; k++) {
                g2 = add2(g2, E2[k]);
                a2 = fma2(E2[k], W2[k], a2);
                E2[k] = mul2(E2[k], R2[k]);     // advance e to next pair
                R2[k] = mul2(R2[k], Q2[k]);     // advance the ratio
            }
            float glo, ghi, alo, ahi;
            upk2(g2, glo, ghi);
            upk2(a2, alo, ahi);
            rp[2 * q]     = __saturatef(__fdividef(alo, fmaxf(glo, 1e-7f)));
            rp[2 * q + 1] = __saturatef(__fdividef(ahi, fmaxf(ghi, 1e-7f)));
        }
        // p0 is a multiple of 32 -> aligned float4 stores, issued as ready
        *reinterpret_cast<float4*>(dst + 4 * v) = r4;
    }
}

extern "C" void kernel_launch(void* const* d_in, const int* in_sizes, int n_in,
                              void* d_out, int out_size) {
    const float* params = nullptr;
    for (int idx = 0; idx < n_in; idx++) {
        if (in_sizes[idx] == NBATCH * NPAR) params = (const float*)d_in[idx];
    }
    if (!params) params = (const float*)d_in[n_in - 1];

    float* out = (float*)d_out;
    dim3 grid(PIX / PPB, NBATCH);      // (8, 128) = 1024 blocks
    moe_gauss_kernel<<<grid, THREADS>>>(params, out);
}